// round 16
// baseline (speedup 1.0000x reference)
#include <cuda_runtime.h>
#include <cuda_bf16.h>
#include <mma.h>
#include <math.h>
#include <stdint.h>

using namespace nvcuda;

#define NB    8
#define RTOT  131072
#define DX    512
#define MT    128
#define GRID_MAIN (RTOT/MT)   // 1024

// ---------------- device scratch ----------------
__device__ float g_q[(size_t)RTOT*32];     // q-hat fp32
__device__ float g_S[NB*32*DX];
__device__ float g_ksum[NB*32];
__device__ float g_T[NB*2048];
__device__ float g_kvn[NB*2048];
__device__ float g_bqk[64];
__device__ float g_B1[8*4096];             // pass1 B [ch][64k][64n], tf32-rounded fp32
__device__ float g_Bo[NB*40*512];          // k_out B [b][40k][512n], tf32-rounded
                                           //   rows 0..31 = M2, row 32 = bout, 33..39 = 0

// ---------------- helpers ----------------
__device__ __forceinline__ unsigned smem_u32(const void* p){
    unsigned r;
    asm("{.reg .u64 t; cvta.to.shared.u64 t,%1; cvt.u32.u64 %0,t;}":"=r"(r):"l"(p));
    return r;
}
__device__ __forceinline__ void cpa16(unsigned s, const void* g){
    asm volatile("cp.async.cg.shared.global [%0],[%1],16;"::"r"(s),"l"(g));
}
#define CPA_COMMIT() asm volatile("cp.async.commit_group;")
#define CPA_WAIT0()  asm volatile("cp.async.wait_group 0;")

// round-to-nearest-even TF32 (RNA) — unbiased; HW truncation (RTZ) would bias
__device__ __forceinline__ float tf32r(float f){
    float o; asm("cvt.rna.tf32.f32 %0,%1;":"=f"(o):"f"(f)); return o;
}

// ---------------- zero accumulators + static rows of k_out B ----------------
__global__ void k_zero(const float* __restrict__ bout){
    int i = blockIdx.x*256 + threadIdx.x;     // grid 512*256 = 131072
    if (i < NB*32*DX) g_S[i] = 0.0f;
    if (i < NB*2048)  g_T[i] = 0.0f;
    if (i < NB*32)    g_ksum[i] = 0.0f;
    if (i < NB*8*512){                         // rows 32..39 of k_out B
        int b = i >> 12, rem = i & 4095;
        int k = 32 + (rem >> 9), d = rem & 511;
        g_Bo[((size_t)b*40 + k)*512 + d] = (k == 32) ? tf32r(bout[d]) : 0.0f;
    }
}

// ---------------- fold weights -> tf32-rounded B chunks + bias ----------------
__global__ void k_combine(const float* __restrict__ Win, const float* __restrict__ bin,
                          const float* __restrict__ Wq,  const float* __restrict__ Wk){
    int idx = blockIdx.x*256 + threadIdx.x;
    if (idx < DX*64){
        int i = idx >> 6, j = idx & 63;        // i: K, j: col
        int h = (j >> 2) & 7, r = j & 3;
        const float* W = (j < 32) ? Wq : Wk;
        float s = 0.f;
        #pragma unroll 8
        for (int d = 0; d < 64; d++) s += Win[(size_t)i*DX + h*64 + d] * W[d*4 + r];
        int ch = i >> 6;
        g_B1[ch*4096 + (i & 63)*64 + j] = tf32r(s);
    } else if (idx < DX*64 + 64){
        int j = idx - DX*64;
        int h = (j >> 2) & 7, r = j & 3;
        const float* W = (j < 32) ? Wq : Wk;
        float s = 0.f;
        #pragma unroll 8
        for (int d = 0; d < 64; d++) s += bin[h*64 + d] * W[d*4 + r];
        g_bqk[j] = s;
    }
}

// ---------------- main kernel: tf32 wmma logits + softmax/exp + tf32 S accum ----
// bytes: XS [0,36864)      x tile [128][72] fp32 (tf32-rounded); reused as Cs
//        WQ [36864,55296)  B tile [64][72]; reused as Ss [32][72] in pass3
//        EK [55296,72704)  ekT [32][136] fp32 (tf32-rounded)
//        BQ [72704,72960)
#define SM_MAIN 72960

__global__ __launch_bounds__(256, 2)
void k_main(const float* __restrict__ x){
    extern __shared__ __align__(1024) unsigned char smraw[];
    const unsigned sbase = smem_u32(smraw);
    float* XS  = (float*)(smraw);
    float* WQ  = (float*)(smraw + 36864);
    float* EK  = (float*)(smraw + 55296);
    float* bqs = (float*)(smraw + 72704);
    float* Cs  = XS;
    float* Ss  = WQ;

    const int tid = threadIdx.x, wid = tid >> 5;
    const int blk = blockIdx.x, row0 = blk * MT, b = blk >> 7;

    if (tid < 64) bqs[tid] = g_bqk[tid];

    float4 xr[8];
    #define LDGX(ch) { _Pragma("unroll") for (int i = 0; i < 8; i++){ \
        int idx = tid + i*256; int r = idx >> 4, c = idx & 15; \
        xr[i] = *(const float4*)&x[(size_t)(row0 + r)*DX + (ch)*64 + c*4]; } }
    #define STS_X() { _Pragma("unroll") for (int i = 0; i < 8; i++){ \
        int idx = tid + i*256; int r = idx >> 4, c = idx & 15; \
        float4 v; v.x = tf32r(xr[i].x); v.y = tf32r(xr[i].y); \
        v.z = tf32r(xr[i].z); v.w = tf32r(xr[i].w); \
        *(float4*)&XS[r*72 + c*4] = v; } }

    // ============ pass 1: logits[128x64] = x @ Wqkc (tf32) ============
    {
        wmma::fragment<wmma::accumulator,16,16,8,float> acc[4];
        #pragma unroll
        for (int nt = 0; nt < 4; nt++) wmma::fill_fragment(acc[nt], 0.0f);

        LDGX(0);
        #pragma unroll 1
        for (int ch = 0; ch < 8; ch++){
            if (ch) __syncthreads();
            STS_X();
            {   // stage B chunk [64k][64n] -> WQ [64][72] via cp.async
                const float* gb = g_B1 + ch*4096;
                #pragma unroll
                for (int i = 0; i < 4; i++){
                    int idx = tid + i*256;
                    int k = idx >> 4, c4 = idx & 15;
                    cpa16(sbase + 36864u + (unsigned)(k*72 + c4*4)*4u,
                          gb + k*64 + c4*4);
                }
                CPA_COMMIT();
            }
            if (ch < 7) LDGX(ch + 1);
            CPA_WAIT0();
            __syncthreads();

            const float* Ap = XS + wid*16*72;
            #pragma unroll
            for (int ks = 0; ks < 8; ks++){
                wmma::fragment<wmma::matrix_a,16,16,8,wmma::precision::tf32,wmma::row_major> a;
                wmma::load_matrix_sync(a, Ap + ks*8, 72);
                #pragma unroll
                for (int nt = 0; nt < 4; nt++){
                    wmma::fragment<wmma::matrix_b,16,16,8,wmma::precision::tf32,wmma::row_major> bb;
                    wmma::load_matrix_sync(bb, WQ + ks*8*72 + nt*16, 72);
                    wmma::mma_sync(acc[nt], a, bb, acc[nt]);
                }
            }
        }
        __syncthreads();
        #pragma unroll
        for (int nt = 0; nt < 4; nt++)
            wmma::store_matrix_sync(Cs + wid*16*72 + nt*16, acc[nt], 72, wmma::mem_row_major);
        __syncthreads();
    }

    // ============ epilogue: softmax(q) -> g_q ; exp(k) -> ekT (tf32) ============
    if (tid < 128){
        const int r = tid;
        const float* crow = Cs + r*72;
        size_t n = (size_t)row0 + r;
        #pragma unroll
        for (int h = 0; h < 8; h++){
            float v0 = crow[h*4+0] + bqs[h*4+0];
            float v1 = crow[h*4+1] + bqs[h*4+1];
            float v2 = crow[h*4+2] + bqs[h*4+2];
            float v3 = crow[h*4+3] + bqs[h*4+3];
            float m = fmaxf(fmaxf(v0, v1), fmaxf(v2, v3));
            float e0 = expf(v0-m), e1 = expf(v1-m), e2 = expf(v2-m), e3 = expf(v3-m);
            float inv = 1.0f/(e0+e1+e2+e3);
            float4 qv; qv.x = e0*inv; qv.y = e1*inv; qv.z = e2*inv; qv.w = e3*inv;
            *(float4*)&g_q[n*32 + h*4] = qv;
        }
        #pragma unroll
        for (int j = 0; j < 32; j++)
            EK[j*136 + r] = tf32r(expf(crow[32 + j] + bqs[32 + j]));
    }
    __syncthreads();

    // ksum partials (sums exactly the tf32-rounded E the MMA consumes)
    if (tid < 32){
        const float* er = EK + tid*136;
        float s = 0.f;
        #pragma unroll 8
        for (int r = 0; r < 128; r++) s += er[r];
        atomicAdd(&g_ksum[b*32 + tid], s);
    }

    // ============ pass 3: S += ekT @ x (tf32), chunked over 64 cols ============
    const int mt = wid >> 2, nt3 = wid & 3;
    LDGX(0);
    #pragma unroll 1
    for (int ch = 0; ch < 8; ch++){
        if (ch) __syncthreads();     // prior atomics done with Ss; XS free
        STS_X();
        if (ch < 7) LDGX(ch + 1);
        __syncthreads();

        wmma::fragment<wmma::accumulator,16,16,8,float> sacc;
        wmma::fill_fragment(sacc, 0.0f);
        const float* Ep = EK + mt*16*136;
        const float* Xp = XS + nt3*16;
        #pragma unroll
        for (int ks = 0; ks < 16; ks++){
            wmma::fragment<wmma::matrix_a,16,16,8,wmma::precision::tf32,wmma::row_major> ea;
            wmma::load_matrix_sync(ea, Ep + ks*8, 136);
            wmma::fragment<wmma::matrix_b,16,16,8,wmma::precision::tf32,wmma::row_major> xb;
            wmma::load_matrix_sync(xb, Xp + ks*8*72, 72);
            wmma::mma_sync(sacc, ea, xb, sacc);
        }
        __syncthreads();
        wmma::store_matrix_sync(Ss + mt*16*72 + nt3*16, sacc, 72, wmma::mem_row_major);
        __syncthreads();

        {
            const int hr = tid >> 3, c0 = (tid & 7)*8;
            float* Sb = &g_S[b*16384 + hr*512 + ch*64 + c0];
            const float* sp = &Ss[hr*72 + c0];
            #pragma unroll
            for (int i = 0; i < 8; i++) atomicAdd(&Sb[i], sp[i]);
        }
    }
    #undef LDGX
    #undef STS_X
}

// ---------------- T += S @ Win(head cols), split-K x8 ----------------
__global__ void k_T(const float* __restrict__ Win){
    __shared__ float Ss[4*64];
    const int bh = blockIdx.x >> 3, ks = blockIdx.x & 7;
    const int b = bh >> 3, h = bh & 7;
    const int tid = threadIdx.x;
    const int i0 = ks * 64;
    if (tid < 256){
        int r = tid >> 6, i = tid & 63;
        Ss[r*64 + i] = g_S[b*16384 + (h*4 + r)*512 + i0 + i];
    }
    __syncthreads();
    const int r = tid >> 6, d = tid & 63;
    const float* W = &Win[(size_t)i0*DX + h*64 + d];
    float s = 0.f;
    #pragma unroll 16
    for (int i = 0; i < 64; i++) s += Ss[r*64 + i] * W[(size_t)i*DX];
    atomicAdd(&g_T[b*2048 + (h*4 + r)*64 + d], s);
}

// ---------------- kv_norm = ((T + ksum*bin) @ Wv) / ksum ----------------
__global__ void k_kv(const float* __restrict__ Wv, const float* __restrict__ bin){
    __shared__ float Ts[2048], Wvs[4096], ks[32];
    int b = blockIdx.x, tid = threadIdx.x;
    if (tid < 32) ks[tid] = g_ksum[b*32 + tid];
    for (int i = tid; i < 4096; i += 256) Wvs[i] = Wv[i];
    __syncthreads();
    for (int i = tid; i < 2048; i += 256)
        Ts[i] = g_T[b*2048 + i] + ks[i >> 6] * bin[(i >> 8)*64 + (i & 63)];
    __syncthreads();
    int hr = tid >> 3, cs = tid & 7;
    float acc[8] = {0,0,0,0,0,0,0,0};
    #pragma unroll 4
    for (int d = 0; d < 64; d++){
        float t = Ts[hr*64 + d];
        #pragma unroll
        for (int c = 0; c < 8; c++) acc[c] += t * Wvs[d*64 + cs*8 + c];
    }
    float inv = 1.0f / ks[hr];
    #pragma unroll
    for (int c = 0; c < 8; c++) g_kvn[b*2048 + hr*64 + cs*8 + c] = acc[c] * inv;
}

// ---------------- M2 = kv_norm @ Wout -> tf32-rounded rows 0..31 of k_out B ----
__global__ void k_M2(const float* __restrict__ Wout){
    __shared__ float kvs[2048];
    int b = blockIdx.x >> 2, q4 = blockIdx.x & 3;
    int tid = threadIdx.x;
    for (int i = tid; i < 2048; i += 256) kvs[i] = g_kvn[b*2048 + i];
    __syncthreads();
    int hr = tid >> 3, dg = tid & 7, h = hr >> 2;
    int dout0 = q4*128 + dg*16;
    float acc[16];
    #pragma unroll
    for (int i = 0; i < 16; i++) acc[i] = 0.f;
    #pragma unroll 2
    for (int c = 0; c < 64; c++){
        float kv = kvs[hr*64 + c];
        const float* wrow = &Wout[(size_t)(h*64 + c)*DX + dout0];
        #pragma unroll
        for (int i = 0; i < 16; i++) acc[i] += kv * wrow[i];
    }
    size_t base = ((size_t)b*40 + hr)*512 + dout0;
    #pragma unroll
    for (int i = 0; i < 16; i++) g_Bo[base + i] = tf32r(acc[i]);
}

// ---------------- output: out = [qhat|1] @ [M2;bout] (tf32, bias in K) ----------
// bytes: AQ [0,20480)   A [128][40] fp32
//        BO [20480,62720)  B half [40][264] fp32
#define SM_OUT 62720

__global__ __launch_bounds__(256, 2)
void k_out(float* __restrict__ out){
    extern __shared__ __align__(1024) unsigned char smraw[];
    const unsigned sbase = smem_u32(smraw);
    float* AQ = (float*)(smraw);
    float* BO = (float*)(smraw + 20480);

    const int tid = threadIdx.x, wid = tid >> 5;
    const int blk = blockIdx.x, row0 = blk * MT, b = blk >> 7;

    // build A [128][40]: cols 0..31 = tf32(qhat), col 32 = 1, 33..39 = 0
    #pragma unroll
    for (int i = 0; i < 4; i++){
        int idx = tid + i*256; int r = idx >> 3, c = idx & 7;
        float4 q = *(const float4*)&g_q[((size_t)row0 + r)*32 + c*4];
        float4 v; v.x = tf32r(q.x); v.y = tf32r(q.y); v.z = tf32r(q.z); v.w = tf32r(q.w);
        *(float4*)&AQ[r*40 + c*4] = v;
    }
    #pragma unroll
    for (int i = 0; i < 4; i++){
        int idx = tid + i*256; int r = idx >> 3, c8 = idx & 7;
        AQ[r*40 + 32 + c8] = (c8 == 0) ? 1.0f : 0.0f;
    }

    const float* Ap = AQ + wid*16*40;

    #pragma unroll 1
    for (int half = 0; half < 2; half++){
        {   // stage B half [40][256] -> BO [40][264]
            const float* gb = g_Bo + (size_t)b*40*512 + half*256;
            #pragma unroll
            for (int i = 0; i < 10; i++){
                int idx = tid + i*256;             // 2560 x 16B
                int k = idx >> 6, c4 = idx & 63;
                cpa16(sbase + 20480u + (unsigned)(k*264 + c4*4)*4u,
                      gb + (size_t)k*512 + c4*4);
            }
            CPA_COMMIT(); CPA_WAIT0();
        }
        __syncthreads();

        #pragma unroll 1
        for (int npass = 0; npass < 2; npass++){
            wmma::fragment<wmma::accumulator,16,16,8,float> acc[8];
            #pragma unroll
            for (int nt = 0; nt < 8; nt++) wmma::fill_fragment(acc[nt], 0.0f);
            #pragma unroll
            for (int ks = 0; ks < 5; ks++){
                wmma::fragment<wmma::matrix_a,16,16,8,wmma::precision::tf32,wmma::row_major> a;
                wmma::load_matrix_sync(a, Ap + ks*8, 40);
                #pragma unroll
                for (int nt = 0; nt < 8; nt++){
                    wmma::fragment<wmma::matrix_b,16,16,8,wmma::precision::tf32,wmma::row_major> bb;
                    wmma::load_matrix_sync(bb, BO + ks*8*264 + npass*128 + nt*16, 264);
                    wmma::mma_sync(acc[nt], a, bb, acc[nt]);
                }
            }
            float* orow = out + ((size_t)row0 + wid*16)*DX + half*256 + npass*128;
            #pragma unroll
            for (int nt = 0; nt < 8; nt++)
                wmma::store_matrix_sync(orow + nt*16, acc[nt], DX, wmma::mem_row_major);
        }
        __syncthreads();   // before restaging B
    }
}

// ---------------- launch ----------------
extern "C" void kernel_launch(void* const* d_in, const int* in_sizes, int n_in,
                              void* d_out, int out_size)
{
    const float* x    = (const float*)d_in[0];
    const float* Win  = (const float*)d_in[1];
    const float* bin  = (const float*)d_in[2];
    const float* Wq   = (const float*)d_in[3];
    const float* Wk   = (const float*)d_in[4];
    const float* Wv   = (const float*)d_in[5];
    const float* Wout = (const float*)d_in[6];
    const float* bout = (const float*)d_in[7];
    float* out = (float*)d_out;

    cudaFuncSetAttribute(k_main, cudaFuncAttributeMaxDynamicSharedMemorySize, SM_MAIN);
    cudaFuncSetAttribute(k_out,  cudaFuncAttributeMaxDynamicSharedMemorySize, SM_OUT);

    k_zero<<<512, 256>>>(bout);
    k_combine<<<129, 256>>>(Win, bin, Wq, Wk);
    k_main<<<GRID_MAIN, 256, SM_MAIN>>>(x);
    k_T<<<512, 256>>>(Win);
    k_kv<<<8, 256>>>(Wv, bin);
    k_M2<<<32, 256>>>(Wout);
    k_out<<<GRID_MAIN, 256, SM_OUT>>>(out);
}